// round 14
// baseline (speedup 1.0000x reference)
#include <cuda_runtime.h>
#include <cuda_fp16.h>
#include <cstdint>

// SwitchMoE: N=16384, D=512, F=2048, E=8, top-1 routing, capacity=N.
// R13: mma.sync is at its f32-accum instruction-rate floor (rt~16/SMSP;
// three configs all pinned at tensor=50%). Reduce MMA count 3->2 per k-step:
// 2-term fp16 scheme — A quantized to fp16 (hi only), W as fp16 hi+lo pair
// (22-bit reconstruction). Error = activation quantization ~2.8e-4/GEMM.

#define NT 16384
#define DD 512
#define FF 2048
#define NE 8
#define TMR 256                  // CTA tile rows
#define MAXT (NT / TMR + NE)     // 72

// ---------------- device scratch (no allocation allowed) -------------------
__device__ int   g_top1[NT];
__device__ float g_val[NT];
__device__ int   g_counts[NE];
__device__ float g_denom[NE];
__device__ int   g_cursor[NE];
__device__ int   g_perm[NT];
__device__ int   g_tile_e[MAXT];
__device__ int   g_tile_start[MAXT];
__device__ int   g_tile_rows[MAXT];
__device__ int   g_ntiles;

__device__ __half g_xh[(size_t)NT * DD];                // fp16(x)
__device__ __half g_w1h[(size_t)NE * FF * DD];          // transposed [E][F][D]
__device__ __half g_w1l[(size_t)NE * FF * DD];
__device__ __half g_w2h[(size_t)NE * DD * FF];          // transposed [E][D][F]
__device__ __half g_w2l[(size_t)NE * DD * FF];
__device__ __half g_Hh[(size_t)NT * FF];                // fp16(relu(xW1+b1))

// ---------------- PTX helpers (compute_80+ generic) ------------------------
__device__ __forceinline__ uint32_t smem_u32(const void* p) {
    uint32_t a;
    asm("{ .reg .u64 t; cvta.to.shared.u64 t, %1; cvt.u32.u64 %0, t; }"
        : "=r"(a) : "l"(p));
    return a;
}
__device__ __forceinline__ void cpa16(uint32_t s, const void* g) {
    asm volatile("cp.async.cg.shared.global [%0], [%1], 16;" :: "r"(s), "l"(g));
}
#define CPA_COMMIT() asm volatile("cp.async.commit_group;" ::: "memory")
#define CPA_WAIT(n)  asm volatile("cp.async.wait_group %0;" :: "n"(n) : "memory")

__device__ __forceinline__ void ldmx4(uint32_t* r, uint32_t addr) {
    asm volatile("ldmatrix.sync.aligned.m8n8.x4.shared.b16 {%0,%1,%2,%3}, [%4];"
                 : "=r"(r[0]), "=r"(r[1]), "=r"(r[2]), "=r"(r[3]) : "r"(addr));
}
__device__ __forceinline__ void mma_f16(float* c, const uint32_t* a, const uint32_t* b) {
    asm volatile(
        "mma.sync.aligned.m16n8k16.row.col.f32.f16.f16.f32 "
        "{%0,%1,%2,%3}, {%4,%5,%6,%7}, {%8,%9}, {%0,%1,%2,%3};"
        : "+f"(c[0]), "+f"(c[1]), "+f"(c[2]), "+f"(c[3])
        : "r"(a[0]), "r"(a[1]), "r"(a[2]), "r"(a[3]), "r"(b[0]), "r"(b[1]));
}

__device__ __forceinline__ void split_f16(float v, __half& hi, __half& lo) {
    hi = __float2half_rn(v);
    lo = __float2half_rn(v - __half2float(hi));
}

// ---------------- launch 1: convert x + W1 (+ zero counters) ---------------
// blocks [0, 4096): x -> fp16      (16384*512 / 2048 elems per block)
// blocks [4096, 12288): W1 transpose+split [E][D][F] -> [E][F][D] hi/lo
__global__ void k_cvt_a(const float* __restrict__ x, const float* __restrict__ W1) {
    const int tid = threadIdx.x;
    if (blockIdx.x < 4096) {
        if (blockIdx.x == 0 && tid < NE) { g_counts[tid] = 0; g_cursor[tid] = 0; }
        size_t i = ((size_t)blockIdx.x * 256 + tid) * 8;
        float4 v0 = *(const float4*)(x + i);
        float4 v1 = *(const float4*)(x + i + 4);
        union { __half h[8]; uint4 u; } H;
        H.h[0] = __float2half_rn(v0.x); H.h[1] = __float2half_rn(v0.y);
        H.h[2] = __float2half_rn(v0.z); H.h[3] = __float2half_rn(v0.w);
        H.h[4] = __float2half_rn(v1.x); H.h[5] = __float2half_rn(v1.y);
        H.h[6] = __float2half_rn(v1.z); H.h[7] = __float2half_rn(v1.w);
        *(uint4*)(g_xh + i) = H.u;
    } else {
        __shared__ float t[32][33];
        const int bi = blockIdx.x - 4096;
        const int e = bi >> 10;          // 1024 blocks per expert
        const int rem = bi & 1023;
        const int c0 = (rem & 63) * 32;  // col block in F
        const int r0 = (rem >> 6) * 32;  // row block in D
        const int tx = tid & 31, ty = tid >> 5;
        const float* src = W1 + ((size_t)e * DD + r0) * FF + c0;
#pragma unroll
        for (int i = 0; i < 4; i++)
            t[ty + i * 8][tx] = src[(size_t)(ty + i * 8) * FF + tx];
        __syncthreads();
#pragma unroll
        for (int i = 0; i < 4; i++) {
            float v = t[tx][ty + i * 8];
            __half hi, lo;
            split_f16(v, hi, lo);
            size_t o = ((size_t)e * FF + c0 + ty + i * 8) * DD + r0 + tx;
            g_w1h[o] = hi; g_w1l[o] = lo;
        }
    }
}

// ---------------- launch 2: router -----------------------------------------
__global__ void k_router(const float* __restrict__ x, const float* __restrict__ Wg) {
    __shared__ float sWg[NE * DD];
    for (int i = threadIdx.x; i < NE * DD; i += 256) sWg[i] = Wg[i];
    __syncthreads();
    const int warp = threadIdx.x >> 5, lane = threadIdx.x & 31;
    const int n = blockIdx.x * 8 + warp;
    const float* xr = x + (size_t)n * DD;
    float acc[NE];
#pragma unroll
    for (int e = 0; e < NE; e++) acc[e] = 0.f;
    for (int k = lane; k < DD; k += 32) {
        float xv = xr[k];
#pragma unroll
        for (int e = 0; e < NE; e++) acc[e] = fmaf(xv, sWg[e * DD + k], acc[e]);
    }
#pragma unroll
    for (int e = 0; e < NE; e++)
#pragma unroll
        for (int o = 16; o; o >>= 1) acc[e] += __shfl_xor_sync(0xffffffffu, acc[e], o);
    if (lane == 0) {
        float best = acc[0]; int be = 0;
#pragma unroll
        for (int e = 1; e < NE; e++) if (acc[e] > best) { best = acc[e]; be = e; }
        g_top1[n] = be;
        g_val[n]  = best;
        atomicAdd(&g_counts[be], 1);
    }
}

// ---------------- launch 3: fused denom + tile build + scatter --------------
__global__ void k_fuse() {
    const int b = blockIdx.x, tid = threadIdx.x;
    int offs[NE]; int off = 0;
#pragma unroll
    for (int e = 0; e < NE; e++) { offs[e] = off; off += g_counts[e]; }

    const int n = b * 256 + tid;
    const int e = g_top1[n];
    const int pos = atomicAdd(&g_cursor[e], 1);
    g_perm[offs[e] + pos] = n;

    if (b < NE) {
        __shared__ float s[256];
        float p = 0.f;
        for (int i = tid; i < NT; i += 256)
            if (g_top1[i] == b) p += g_val[i];
        s[tid] = p;
        __syncthreads();
        for (int st = 128; st > 0; st >>= 1) {
            if (tid < st) s[tid] += s[tid + st];
            __syncthreads();
        }
        if (tid == 0) g_denom[b] = s[0] + 1e-6f;
    } else if (b == NE && tid == 0) {
        int t = 0;
#pragma unroll
        for (int e2 = 0; e2 < NE; e2++) {
            int c = g_counts[e2];
            for (int r = 0; r < c; r += TMR) {
                g_tile_e[t] = e2; g_tile_start[t] = offs[e2] + r;
                g_tile_rows[t] = (c - r < TMR) ? (c - r) : TMR;
                t++;
            }
        }
        g_ntiles = t;
    }
}

// ---------------- launch 5: convert W2 --------------------------------------
__global__ void k_cvt_w2(const float* __restrict__ W2) {
    __shared__ float t[32][33];
    const int e = blockIdx.z;
    const int c0 = blockIdx.x * 32, r0 = blockIdx.y * 32;   // c in D, r in F
    const int tx = threadIdx.x, ty = threadIdx.y;
    const float* src = W2 + ((size_t)e * FF + r0) * DD + c0;
#pragma unroll
    for (int i = 0; i < 4; i++)
        t[ty + i * 8][tx] = src[(size_t)(ty + i * 8) * DD + tx];
    __syncthreads();
#pragma unroll
    for (int i = 0; i < 4; i++) {
        float v = t[tx][ty + i * 8];
        __half hi, lo;
        split_f16(v, hi, lo);
        size_t o = ((size_t)e * DD + c0 + ty + i * 8) * FF + r0 + tx;
        g_w2h[o] = hi; g_w2l[o] = lo;
    }
}

// ---------------- launches 4 & 6: persistent mma.sync GEMM ------------------
// CTA: 512 threads (16 warps), CTA tile 256x128, warp grid 4(M)x4(N),
// warp tile 64x32. K-chunk 32, 3-stage cp.async pipeline.
// Per k-step: 2 MMAs (A_hi x B_hi + A_hi x B_lo).
#define ROWB 80
#define A_BYTES 20480              // 256 * 80 (A hi only)
#define B_BYTES 10240              // 128 * 80
#define STG_BYTES (A_BYTES + 2 * B_BYTES)  // 40960
#define NSTG 3
#define DSMEM (NSTG * STG_BYTES)   // 122880
#define NPERS 148

template <int G>
__global__ __launch_bounds__(512, 1) void k_mma(const float* __restrict__ bias,
                                                float* __restrict__ outp) {
    constexpr int KTOT = (G == 1) ? DD : FF;
    constexpr int NTOT = (G == 1) ? FF : DD;
    constexpr int NKC  = KTOT / 32;
    constexpr int NNY  = NTOT / 128;

    const __half* A  = (G == 1) ? g_xh : g_Hh;
    const __half* Bh = (G == 1) ? g_w1h : g_w2h;
    const __half* Bl = (G == 1) ? g_w1l : g_w2l;

    extern __shared__ char smem[];
    __shared__ int   sPerm[TMR];
    __shared__ float sBias[128];
    const uint32_t dbase = smem_u32(smem);

    const int tid = threadIdx.x;
    const int wid = tid >> 5, lane = tid & 31;
    const int wm = wid & 3, wn = wid >> 2;   // warp tile: rows wm*64, cols wn*32
    // A load slots: 1024 (256 rows x 4 segs), 2 per thread
    const int lrowA0 = tid >> 2, lrowA1 = (tid + 512) >> 2, lseg = tid & 3;
    const uint32_t lsoA0 = lrowA0 * ROWB + lseg * 16;
    const uint32_t lsoA1 = lrowA1 * ROWB + lseg * 16;
    // B load slots: 512 (128 rows x 4 segs), 1 per thread per array
    const int lrowB = tid >> 2;
    const uint32_t lsoB = lrowB * ROWB + lseg * 16;
    const uint32_t aLane = (uint32_t)(wm * 64 + (lane & 15)) * ROWB + ((lane & 16) ? 16 : 0);
    const uint32_t bLane = (uint32_t)(wn * 32 + (lane & 7) + ((lane & 16) ? 8 : 0)) * ROWB
                         + ((lane & 8) ? 16 : 0);
    const int rquad = lane >> 2, cpair = (lane & 3) * 2;

    const int nwork = g_ntiles * NNY;
    for (int w = blockIdx.x; w < nwork; w += NPERS) {
        const int tile = w / NNY, ny = w % NNY;
        const int e     = g_tile_e[tile];
        const int start = g_tile_start[tile];
        const int rows  = g_tile_rows[tile];
        const int n0    = ny * 128;

        __syncthreads();
        if (tid < TMR)
            sPerm[tid] = g_perm[start + (tid < rows ? tid : rows - 1)];
        if (tid < 128)
            sBias[tid] = bias[(size_t)e * NTOT + n0 + tid];
        __syncthreads();

        const __half *pA0, *pA1, *pBh, *pBl;
        {
            pA0 = A + (size_t)sPerm[lrowA0] * KTOT + lseg * 8;
            pA1 = A + (size_t)sPerm[lrowA1] * KTOT + lseg * 8;
            size_t b0 = ((size_t)e * NTOT + n0 + lrowB) * KTOT + lseg * 8;
            pBh = Bh + b0; pBl = Bl + b0;
        }

        auto load_stage = [&](int c, int s) {
            const int k0 = c * 32;
            const uint32_t d = dbase + s * STG_BYTES;
            cpa16(d + lsoA0,                    pA0 + k0);
            cpa16(d + lsoA1,                    pA1 + k0);
            cpa16(d + A_BYTES + lsoB,           pBh + k0);
            cpa16(d + A_BYTES + B_BYTES + lsoB, pBl + k0);
        };

        float acc[4][4][4];
#pragma unroll
        for (int mi = 0; mi < 4; mi++)
#pragma unroll
            for (int ni = 0; ni < 4; ni++)
#pragma unroll
                for (int q = 0; q < 4; q++) acc[mi][ni][q] = 0.f;

        auto compute = [&](int s) {
            const uint32_t b0 = dbase + s * STG_BYTES;
#pragma unroll
            for (int kh = 0; kh < 2; kh++) {
                const uint32_t khb = kh * 32;
                uint32_t ah[4][4], bh[2][4], bl[2][4];
#pragma unroll
                for (int mi = 0; mi < 4; mi++)
                    ldmx4(ah[mi], b0 + aLane + mi * (16 * ROWB) + khb);
#pragma unroll
                for (int p = 0; p < 2; p++) {
                    ldmx4(bh[p], b0 + A_BYTES + bLane + p * (16 * ROWB) + khb);
                    ldmx4(bl[p], b0 + A_BYTES + B_BYTES + bLane + p * (16 * ROWB) + khb);
                }
#pragma unroll
                for (int mi = 0; mi < 4; mi++)
#pragma unroll
                    for (int ni = 0; ni < 4; ni++)
                        mma_f16(acc[mi][ni], ah[mi], &bh[ni >> 1][(ni & 1) * 2]);
#pragma unroll
                for (int mi = 0; mi < 4; mi++)
#pragma unroll
                    for (int ni = 0; ni < 4; ni++)
                        mma_f16(acc[mi][ni], ah[mi], &bl[ni >> 1][(ni & 1) * 2]);
            }
        };

        load_stage(0, 0); CPA_COMMIT();
        load_stage(1, 1); CPA_COMMIT();
        for (int c = 0; c < NKC; c++) {
            if (c == NKC - 1) { CPA_WAIT(0); } else { CPA_WAIT(1); }
            __syncthreads();
            if (c + 2 < NKC) { load_stage(c + 2, (c + 2) % NSTG); CPA_COMMIT(); }
            compute(c % NSTG);
        }

        // ---- epilogue ----
#pragma unroll
        for (int mi = 0; mi < 4; mi++) {
#pragma unroll
            for (int half = 0; half < 2; half++) {
                const int r = wm * 64 + mi * 16 + rquad + half * 8;
                if (r < rows) {
                    const int token = sPerm[r];
                    if (G == 1) {
#pragma unroll
                        for (int ni = 0; ni < 4; ni++) {
                            const int col = wn * 32 + ni * 8 + cpair;
                            float v0 = fmaxf(acc[mi][ni][half * 2 + 0] + sBias[col], 0.f);
                            float v1 = fmaxf(acc[mi][ni][half * 2 + 1] + sBias[col + 1], 0.f);
                            union { __half h[2]; uint32_t u; } H;
                            H.h[0] = __float2half_rn(v0);
                            H.h[1] = __float2half_rn(v1);
                            *(uint32_t*)(g_Hh + (size_t)token * FF + n0 + col) = H.u;
                        }
                    } else {
                        const float sc = g_val[token] / g_denom[e] * 16384.0f;
#pragma unroll
                        for (int ni = 0; ni < 4; ni++) {
                            const int col = wn * 32 + ni * 8 + cpair;
                            float2 v;
                            v.x = sc * (acc[mi][ni][half * 2 + 0] + sBias[col]);
                            v.y = sc * (acc[mi][ni][half * 2 + 1] + sBias[col + 1]);
                            *(float2*)(outp + (size_t)token * DD + n0 + col) = v;
                        }
                    }
                }
            }
        }
    }
}

// ---------------------------------------------------------------------------
extern "C" void kernel_launch(void* const* d_in, const int* in_sizes, int n_in,
                              void* d_out, int out_size) {
    const float* x  = (const float*)d_in[0];
    const float* Wg = (const float*)d_in[1];
    const float* W1 = (const float*)d_in[2];
    const float* b1 = (const float*)d_in[3];
    const float* W2 = (const float*)d_in[4];
    const float* b2 = (const float*)d_in[5];
    float* out = (float*)d_out;

    static bool configured = false;
    if (!configured) {
        cudaFuncSetAttribute(k_mma<1>, cudaFuncAttributeMaxDynamicSharedMemorySize, DSMEM);
        cudaFuncSetAttribute(k_mma<2>, cudaFuncAttributeMaxDynamicSharedMemorySize, DSMEM);
        configured = true;
    }

    k_cvt_a<<<12288, 256>>>(x, W1);                             // 1
    k_router<<<NT / 8, 256>>>(x, Wg);                           // 2
    k_fuse<<<64, 256>>>();                                      // 3
    k_mma<1><<<NPERS, 512, DSMEM>>>(b1, nullptr);               // 4  <- ncu capture
    k_cvt_w2<<<dim3(DD / 32, FF / 32, NE), dim3(32, 8)>>>(W2);  // 5
    k_mma<2><<<NPERS, 512, DSMEM>>>(b2, out);                   // 6
}

// round 15
// speedup vs baseline: 1.4497x; 1.4497x over previous
#include <cuda_runtime.h>
#include <cuda_fp16.h>
#include <cstdint>

// SwitchMoE: N=16384, D=512, F=2048, E=8, top-1 routing, capacity=N.
// R14: K-loop is latency-bound (4 structurally different kernels all at
// ~375us, no pipe >52%). Pipeline depth 3 -> 5 stages (lookahead 2 -> 4
// chunks) with empty-commit tail handling. Rest identical to R13
// (2-term fp16: A=fp16, W=fp16 hi+lo).

#define NT 16384
#define DD 512
#define FF 2048
#define NE 8
#define TMR 256                  // CTA tile rows
#define MAXT (NT / TMR + NE)     // 72

// ---------------- device scratch (no allocation allowed) -------------------
__device__ int   g_top1[NT];
__device__ float g_val[NT];
__device__ int   g_counts[NE];
__device__ float g_denom[NE];
__device__ int   g_cursor[NE];
__device__ int   g_perm[NT];
__device__ int   g_tile_e[MAXT];
__device__ int   g_tile_start[MAXT];
__device__ int   g_tile_rows[MAXT];
__device__ int   g_ntiles;

__device__ __half g_xh[(size_t)NT * DD];                // fp16(x)
__device__ __half g_w1h[(size_t)NE * FF * DD];          // transposed [E][F][D]
__device__ __half g_w1l[(size_t)NE * FF * DD];
__device__ __half g_w2h[(size_t)NE * DD * FF];          // transposed [E][D][F]
__device__ __half g_w2l[(size_t)NE * DD * FF];
__device__ __half g_Hh[(size_t)NT * FF];                // fp16(relu(xW1+b1))

// ---------------- PTX helpers (compute_80+ generic) ------------------------
__device__ __forceinline__ uint32_t smem_u32(const void* p) {
    uint32_t a;
    asm("{ .reg .u64 t; cvta.to.shared.u64 t, %1; cvt.u32.u64 %0, t; }"
        : "=r"(a) : "l"(p));
    return a;
}
__device__ __forceinline__ void cpa16(uint32_t s, const void* g) {
    asm volatile("cp.async.cg.shared.global [%0], [%1], 16;" :: "r"(s), "l"(g));
}
#define CPA_COMMIT() asm volatile("cp.async.commit_group;" ::: "memory")
#define CPA_WAIT(n)  asm volatile("cp.async.wait_group %0;" :: "n"(n) : "memory")

__device__ __forceinline__ void ldmx4(uint32_t* r, uint32_t addr) {
    asm volatile("ldmatrix.sync.aligned.m8n8.x4.shared.b16 {%0,%1,%2,%3}, [%4];"
                 : "=r"(r[0]), "=r"(r[1]), "=r"(r[2]), "=r"(r[3]) : "r"(addr));
}
__device__ __forceinline__ void mma_f16(float* c, const uint32_t* a, const uint32_t* b) {
    asm volatile(
        "mma.sync.aligned.m16n8k16.row.col.f32.f16.f16.f32 "
        "{%0,%1,%2,%3}, {%4,%5,%6,%7}, {%8,%9}, {%0,%1,%2,%3};"
        : "+f"(c[0]), "+f"(c[1]), "+f"(c[2]), "+f"(c[3])
        : "r"(a[0]), "r"(a[1]), "r"(a[2]), "r"(a[3]), "r"(b[0]), "r"(b[1]));
}

__device__ __forceinline__ void split_f16(float v, __half& hi, __half& lo) {
    hi = __float2half_rn(v);
    lo = __float2half_rn(v - __half2float(hi));
}

// ---------------- launch 1: convert x + W1 (+ zero counters) ---------------
__global__ void k_cvt_a(const float* __restrict__ x, const float* __restrict__ W1) {
    const int tid = threadIdx.x;
    if (blockIdx.x < 4096) {
        if (blockIdx.x == 0 && tid < NE) { g_counts[tid] = 0; g_cursor[tid] = 0; }
        size_t i = ((size_t)blockIdx.x * 256 + tid) * 8;
        float4 v0 = *(const float4*)(x + i);
        float4 v1 = *(const float4*)(x + i + 4);
        union { __half h[8]; uint4 u; } H;
        H.h[0] = __float2half_rn(v0.x); H.h[1] = __float2half_rn(v0.y);
        H.h[2] = __float2half_rn(v0.z); H.h[3] = __float2half_rn(v0.w);
        H.h[4] = __float2half_rn(v1.x); H.h[5] = __float2half_rn(v1.y);
        H.h[6] = __float2half_rn(v1.z); H.h[7] = __float2half_rn(v1.w);
        *(uint4*)(g_xh + i) = H.u;
    } else {
        __shared__ float t[32][33];
        const int bi = blockIdx.x - 4096;
        const int e = bi >> 10;
        const int rem = bi & 1023;
        const int c0 = (rem & 63) * 32;
        const int r0 = (rem >> 6) * 32;
        const int tx = tid & 31, ty = tid >> 5;
        const float* src = W1 + ((size_t)e * DD + r0) * FF + c0;
#pragma unroll
        for (int i = 0; i < 4; i++)
            t[ty + i * 8][tx] = src[(size_t)(ty + i * 8) * FF + tx];
        __syncthreads();
#pragma unroll
        for (int i = 0; i < 4; i++) {
            float v = t[tx][ty + i * 8];
            __half hi, lo;
            split_f16(v, hi, lo);
            size_t o = ((size_t)e * FF + c0 + ty + i * 8) * DD + r0 + tx;
            g_w1h[o] = hi; g_w1l[o] = lo;
        }
    }
}

// ---------------- launch 2: router -----------------------------------------
__global__ void k_router(const float* __restrict__ x, const float* __restrict__ Wg) {
    __shared__ float sWg[NE * DD];
    for (int i = threadIdx.x; i < NE * DD; i += 256) sWg[i] = Wg[i];
    __syncthreads();
    const int warp = threadIdx.x >> 5, lane = threadIdx.x & 31;
    const int n = blockIdx.x * 8 + warp;
    const float* xr = x + (size_t)n * DD;
    float acc[NE];
#pragma unroll
    for (int e = 0; e < NE; e++) acc[e] = 0.f;
    for (int k = lane; k < DD; k += 32) {
        float xv = xr[k];
#pragma unroll
        for (int e = 0; e < NE; e++) acc[e] = fmaf(xv, sWg[e * DD + k], acc[e]);
    }
#pragma unroll
    for (int e = 0; e < NE; e++)
#pragma unroll
        for (int o = 16; o; o >>= 1) acc[e] += __shfl_xor_sync(0xffffffffu, acc[e], o);
    if (lane == 0) {
        float best = acc[0]; int be = 0;
#pragma unroll
        for (int e = 1; e < NE; e++) if (acc[e] > best) { best = acc[e]; be = e; }
        g_top1[n] = be;
        g_val[n]  = best;
        atomicAdd(&g_counts[be], 1);
    }
}

// ---------------- launch 3: fused denom + tile build + scatter --------------
__global__ void k_fuse() {
    const int b = blockIdx.x, tid = threadIdx.x;
    int offs[NE]; int off = 0;
#pragma unroll
    for (int e = 0; e < NE; e++) { offs[e] = off; off += g_counts[e]; }

    const int n = b * 256 + tid;
    const int e = g_top1[n];
    const int pos = atomicAdd(&g_cursor[e], 1);
    g_perm[offs[e] + pos] = n;

    if (b < NE) {
        __shared__ float s[256];
        float p = 0.f;
        for (int i = tid; i < NT; i += 256)
            if (g_top1[i] == b) p += g_val[i];
        s[tid] = p;
        __syncthreads();
        for (int st = 128; st > 0; st >>= 1) {
            if (tid < st) s[tid] += s[tid + st];
            __syncthreads();
        }
        if (tid == 0) g_denom[b] = s[0] + 1e-6f;
    } else if (b == NE && tid == 0) {
        int t = 0;
#pragma unroll
        for (int e2 = 0; e2 < NE; e2++) {
            int c = g_counts[e2];
            for (int r = 0; r < c; r += TMR) {
                g_tile_e[t] = e2; g_tile_start[t] = offs[e2] + r;
                g_tile_rows[t] = (c - r < TMR) ? (c - r) : TMR;
                t++;
            }
        }
        g_ntiles = t;
    }
}

// ---------------- launch 5: convert W2 --------------------------------------
__global__ void k_cvt_w2(const float* __restrict__ W2) {
    __shared__ float t[32][33];
    const int e = blockIdx.z;
    const int c0 = blockIdx.x * 32, r0 = blockIdx.y * 32;
    const int tx = threadIdx.x, ty = threadIdx.y;
    const float* src = W2 + ((size_t)e * FF + r0) * DD + c0;
#pragma unroll
    for (int i = 0; i < 4; i++)
        t[ty + i * 8][tx] = src[(size_t)(ty + i * 8) * DD + tx];
    __syncthreads();
#pragma unroll
    for (int i = 0; i < 4; i++) {
        float v = t[tx][ty + i * 8];
        __half hi, lo;
        split_f16(v, hi, lo);
        size_t o = ((size_t)e * DD + c0 + ty + i * 8) * FF + r0 + tx;
        g_w2h[o] = hi; g_w2l[o] = lo;
    }
}

// ---------------- launches 4 & 6: persistent mma.sync GEMM ------------------
// CTA: 512 threads (16 warps), CTA tile 256x128, warp grid 4(M)x4(N),
// warp tile 64x32. K-chunk 32, 5-stage cp.async pipeline (4-chunk lookahead).
#define ROWB 80
#define A_BYTES 20480              // 256 * 80 (A hi only)
#define B_BYTES 10240              // 128 * 80
#define STG_BYTES (A_BYTES + 2 * B_BYTES)  // 40960
#define NSTG 5
#define DSMEM (NSTG * STG_BYTES)   // 204800
#define NPERS 148

template <int G>
__global__ __launch_bounds__(512, 1) void k_mma(const float* __restrict__ bias,
                                                float* __restrict__ outp) {
    constexpr int KTOT = (G == 1) ? DD : FF;
    constexpr int NTOT = (G == 1) ? FF : DD;
    constexpr int NKC  = KTOT / 32;
    constexpr int NNY  = NTOT / 128;

    const __half* A  = (G == 1) ? g_xh : g_Hh;
    const __half* Bh = (G == 1) ? g_w1h : g_w2h;
    const __half* Bl = (G == 1) ? g_w1l : g_w2l;

    extern __shared__ char smem[];
    __shared__ int   sPerm[TMR];
    __shared__ float sBias[128];
    const uint32_t dbase = smem_u32(smem);

    const int tid = threadIdx.x;
    const int wid = tid >> 5, lane = tid & 31;
    const int wm = wid & 3, wn = wid >> 2;   // warp tile: rows wm*64, cols wn*32
    const int lrowA0 = tid >> 2, lrowA1 = (tid + 512) >> 2, lseg = tid & 3;
    const uint32_t lsoA0 = lrowA0 * ROWB + lseg * 16;
    const uint32_t lsoA1 = lrowA1 * ROWB + lseg * 16;
    const int lrowB = tid >> 2;
    const uint32_t lsoB = lrowB * ROWB + lseg * 16;
    const uint32_t aLane = (uint32_t)(wm * 64 + (lane & 15)) * ROWB + ((lane & 16) ? 16 : 0);
    const uint32_t bLane = (uint32_t)(wn * 32 + (lane & 7) + ((lane & 16) ? 8 : 0)) * ROWB
                         + ((lane & 8) ? 16 : 0);
    const int rquad = lane >> 2, cpair = (lane & 3) * 2;

    const int nwork = g_ntiles * NNY;
    for (int w = blockIdx.x; w < nwork; w += NPERS) {
        const int tile = w / NNY, ny = w % NNY;
        const int e     = g_tile_e[tile];
        const int start = g_tile_start[tile];
        const int rows  = g_tile_rows[tile];
        const int n0    = ny * 128;

        __syncthreads();
        if (tid < TMR)
            sPerm[tid] = g_perm[start + (tid < rows ? tid : rows - 1)];
        if (tid < 128)
            sBias[tid] = bias[(size_t)e * NTOT + n0 + tid];
        __syncthreads();

        const __half *pA0, *pA1, *pBh, *pBl;
        {
            pA0 = A + (size_t)sPerm[lrowA0] * KTOT + lseg * 8;
            pA1 = A + (size_t)sPerm[lrowA1] * KTOT + lseg * 8;
            size_t b0 = ((size_t)e * NTOT + n0 + lrowB) * KTOT + lseg * 8;
            pBh = Bh + b0; pBl = Bl + b0;
        }

        auto load_stage = [&](int c, int s) {
            const int k0 = c * 32;
            const uint32_t d = dbase + s * STG_BYTES;
            cpa16(d + lsoA0,                    pA0 + k0);
            cpa16(d + lsoA1,                    pA1 + k0);
            cpa16(d + A_BYTES + lsoB,           pBh + k0);
            cpa16(d + A_BYTES + B_BYTES + lsoB, pBl + k0);
        };

        float acc[4][4][4];
#pragma unroll
        for (int mi = 0; mi < 4; mi++)
#pragma unroll
            for (int ni = 0; ni < 4; ni++)
#pragma unroll
                for (int q = 0; q < 4; q++) acc[mi][ni][q] = 0.f;

        auto compute = [&](int s) {
            const uint32_t b0 = dbase + s * STG_BYTES;
#pragma unroll
            for (int kh = 0; kh < 2; kh++) {
                const uint32_t khb = kh * 32;
                uint32_t ah[4][4], bh[2][4], bl[2][4];
#pragma unroll
                for (int mi = 0; mi < 4; mi++)
                    ldmx4(ah[mi], b0 + aLane + mi * (16 * ROWB) + khb);
#pragma unroll
                for (int p = 0; p < 2; p++) {
                    ldmx4(bh[p], b0 + A_BYTES + bLane + p * (16 * ROWB) + khb);
                    ldmx4(bl[p], b0 + A_BYTES + B_BYTES + bLane + p * (16 * ROWB) + khb);
                }
#pragma unroll
                for (int mi = 0; mi < 4; mi++)
#pragma unroll
                    for (int ni = 0; ni < 4; ni++)
                        mma_f16(acc[mi][ni], ah[mi], &bh[ni >> 1][(ni & 1) * 2]);
#pragma unroll
                for (int mi = 0; mi < 4; mi++)
#pragma unroll
                    for (int ni = 0; ni < 4; ni++)
                        mma_f16(acc[mi][ni], ah[mi], &bl[ni >> 1][(ni & 1) * 2]);
            }
        };

        // prologue: fill NSTG-1 = 4 stages
#pragma unroll
        for (int s = 0; s < NSTG - 1; s++) {
            if (s < NKC) load_stage(s, s);
            CPA_COMMIT();
        }
        // steady state: one commit per iteration (empty at tail) keeps group
        // arithmetic uniform so WAIT(NSTG-2) always retires exactly chunk c.
        for (int c = 0; c < NKC; c++) {
            CPA_WAIT(NSTG - 2);
            __syncthreads();
            if (c + NSTG - 1 < NKC) load_stage(c + NSTG - 1, (c + NSTG - 1) % NSTG);
            CPA_COMMIT();
            compute(c % NSTG);
        }

        // ---- epilogue ----
#pragma unroll
        for (int mi = 0; mi < 4; mi++) {
#pragma unroll
            for (int half = 0; half < 2; half++) {
                const int r = wm * 64 + mi * 16 + rquad + half * 8;
                if (r < rows) {
                    const int token = sPerm[r];
                    if (G == 1) {
#pragma unroll
                        for (int ni = 0; ni < 4; ni++) {
                            const int col = wn * 32 + ni * 8 + cpair;
                            float v0 = fmaxf(acc[mi][ni][half * 2 + 0] + sBias[col], 0.f);
                            float v1 = fmaxf(acc[mi][ni][half * 2 + 1] + sBias[col + 1], 0.f);
                            union { __half h[2]; uint32_t u; } H;
                            H.h[0] = __float2half_rn(v0);
                            H.h[1] = __float2half_rn(v1);
                            *(uint32_t*)(g_Hh + (size_t)token * FF + n0 + col) = H.u;
                        }
                    } else {
                        const float sc = g_val[token] / g_denom[e] * 16384.0f;
#pragma unroll
                        for (int ni = 0; ni < 4; ni++) {
                            const int col = wn * 32 + ni * 8 + cpair;
                            float2 v;
                            v.x = sc * (acc[mi][ni][half * 2 + 0] + sBias[col]);
                            v.y = sc * (acc[mi][ni][half * 2 + 1] + sBias[col + 1]);
                            *(float2*)(outp + (size_t)token * DD + n0 + col) = v;
                        }
                    }
                }
            }
        }
    }
}

// ---------------------------------------------------------------------------
extern "C" void kernel_launch(void* const* d_in, const int* in_sizes, int n_in,
                              void* d_out, int out_size) {
    const float* x  = (const float*)d_in[0];
    const float* Wg = (const float*)d_in[1];
    const float* W1 = (const float*)d_in[2];
    const float* b1 = (const float*)d_in[3];
    const float* W2 = (const float*)d_in[4];
    const float* b2 = (const float*)d_in[5];
    float* out = (float*)d_out;

    static bool configured = false;
    if (!configured) {
        cudaFuncSetAttribute(k_mma<1>, cudaFuncAttributeMaxDynamicSharedMemorySize, DSMEM);
        cudaFuncSetAttribute(k_mma<2>, cudaFuncAttributeMaxDynamicSharedMemorySize, DSMEM);
        configured = true;
    }

    k_cvt_a<<<12288, 256>>>(x, W1);                             // 1
    k_router<<<NT / 8, 256>>>(x, Wg);                           // 2
    k_fuse<<<64, 256>>>();                                      // 3
    k_mma<1><<<NPERS, 512, DSMEM>>>(b1, nullptr);               // 4  <- ncu capture
    k_cvt_w2<<<dim3(DD / 32, FF / 32, NE), dim3(32, 8)>>>(W2);  // 5
    k_mma<2><<<NPERS, 512, DSMEM>>>(b2, out);                   // 6
}

// round 16
// speedup vs baseline: 2.2456x; 1.5490x over previous
#include <cuda_runtime.h>
#include <cuda_fp16.h>
#include <cstdint>

// SwitchMoE: N=16384, D=512, F=2048, E=8, top-1 routing, capacity=N.
// R15: R12/R14 both sit exactly at the f32-accum HMMA issue floor
// (rt=16/SMSP) -> only lever left is fewer MMAs. Pure fp16 A x fp16 W:
// 1 MMA per k-step (floor 126us/GEMM). Predicted rel_err ~4.5e-4
// (4 fp16 quantization sources, RSS of measured 2.1e-4 each).
// K-chunk 64, 4-stage pipeline (216KB smem), half the barriers.

#define NT 16384
#define DD 512
#define FF 2048
#define NE 8
#define TMR 256                  // CTA tile rows
#define MAXT (NT / TMR + NE)     // 72

// ---------------- device scratch (no allocation allowed) -------------------
__device__ int   g_top1[NT];
__device__ float g_val[NT];
__device__ int   g_counts[NE];
__device__ float g_denom[NE];
__device__ int   g_cursor[NE];
__device__ int   g_perm[NT];
__device__ int   g_tile_e[MAXT];
__device__ int   g_tile_start[MAXT];
__device__ int   g_tile_rows[MAXT];
__device__ int   g_ntiles;

__device__ __half g_xh[(size_t)NT * DD];                // fp16(x)
__device__ __half g_w1h[(size_t)NE * FF * DD];          // transposed [E][F][D]
__device__ __half g_w2h[(size_t)NE * DD * FF];          // transposed [E][D][F]
__device__ __half g_Hh[(size_t)NT * FF];                // fp16(relu(xW1+b1))

// ---------------- PTX helpers (compute_80+ generic) ------------------------
__device__ __forceinline__ uint32_t smem_u32(const void* p) {
    uint32_t a;
    asm("{ .reg .u64 t; cvta.to.shared.u64 t, %1; cvt.u32.u64 %0, t; }"
        : "=r"(a) : "l"(p));
    return a;
}
__device__ __forceinline__ void cpa16(uint32_t s, const void* g) {
    asm volatile("cp.async.cg.shared.global [%0], [%1], 16;" :: "r"(s), "l"(g));
}
#define CPA_COMMIT() asm volatile("cp.async.commit_group;" ::: "memory")
#define CPA_WAIT(n)  asm volatile("cp.async.wait_group %0;" :: "n"(n) : "memory")

__device__ __forceinline__ void ldmx4(uint32_t* r, uint32_t addr) {
    asm volatile("ldmatrix.sync.aligned.m8n8.x4.shared.b16 {%0,%1,%2,%3}, [%4];"
                 : "=r"(r[0]), "=r"(r[1]), "=r"(r[2]), "=r"(r[3]) : "r"(addr));
}
__device__ __forceinline__ void mma_f16(float* c, const uint32_t* a, const uint32_t* b) {
    asm volatile(
        "mma.sync.aligned.m16n8k16.row.col.f32.f16.f16.f32 "
        "{%0,%1,%2,%3}, {%4,%5,%6,%7}, {%8,%9}, {%0,%1,%2,%3};"
        : "+f"(c[0]), "+f"(c[1]), "+f"(c[2]), "+f"(c[3])
        : "r"(a[0]), "r"(a[1]), "r"(a[2]), "r"(a[3]), "r"(b[0]), "r"(b[1]));
}

// ---------------- launch 1: convert x + W1 (+ zero counters) ---------------
// blocks [0, 4096): x -> fp16
// blocks [4096, 12288): W1 transpose [E][D][F] -> [E][F][D] fp16
__global__ void k_cvt_a(const float* __restrict__ x, const float* __restrict__ W1) {
    const int tid = threadIdx.x;
    if (blockIdx.x < 4096) {
        if (blockIdx.x == 0 && tid < NE) { g_counts[tid] = 0; g_cursor[tid] = 0; }
        size_t i = ((size_t)blockIdx.x * 256 + tid) * 8;
        float4 v0 = *(const float4*)(x + i);
        float4 v1 = *(const float4*)(x + i + 4);
        union { __half h[8]; uint4 u; } H;
        H.h[0] = __float2half_rn(v0.x); H.h[1] = __float2half_rn(v0.y);
        H.h[2] = __float2half_rn(v0.z); H.h[3] = __float2half_rn(v0.w);
        H.h[4] = __float2half_rn(v1.x); H.h[5] = __float2half_rn(v1.y);
        H.h[6] = __float2half_rn(v1.z); H.h[7] = __float2half_rn(v1.w);
        *(uint4*)(g_xh + i) = H.u;
    } else {
        __shared__ float t[32][33];
        const int bi = blockIdx.x - 4096;
        const int e = bi >> 10;
        const int rem = bi & 1023;
        const int c0 = (rem & 63) * 32;
        const int r0 = (rem >> 6) * 32;
        const int tx = tid & 31, ty = tid >> 5;
        const float* src = W1 + ((size_t)e * DD + r0) * FF + c0;
#pragma unroll
        for (int i = 0; i < 4; i++)
            t[ty + i * 8][tx] = src[(size_t)(ty + i * 8) * FF + tx];
        __syncthreads();
#pragma unroll
        for (int i = 0; i < 4; i++) {
            size_t o = ((size_t)e * FF + c0 + ty + i * 8) * DD + r0 + tx;
            g_w1h[o] = __float2half_rn(t[tx][ty + i * 8]);
        }
    }
}

// ---------------- launch 2: router -----------------------------------------
__global__ void k_router(const float* __restrict__ x, const float* __restrict__ Wg) {
    __shared__ float sWg[NE * DD];
    for (int i = threadIdx.x; i < NE * DD; i += 256) sWg[i] = Wg[i];
    __syncthreads();
    const int warp = threadIdx.x >> 5, lane = threadIdx.x & 31;
    const int n = blockIdx.x * 8 + warp;
    const float* xr = x + (size_t)n * DD;
    float acc[NE];
#pragma unroll
    for (int e = 0; e < NE; e++) acc[e] = 0.f;
    for (int k = lane; k < DD; k += 32) {
        float xv = xr[k];
#pragma unroll
        for (int e = 0; e < NE; e++) acc[e] = fmaf(xv, sWg[e * DD + k], acc[e]);
    }
#pragma unroll
    for (int e = 0; e < NE; e++)
#pragma unroll
        for (int o = 16; o; o >>= 1) acc[e] += __shfl_xor_sync(0xffffffffu, acc[e], o);
    if (lane == 0) {
        float best = acc[0]; int be = 0;
#pragma unroll
        for (int e = 1; e < NE; e++) if (acc[e] > best) { best = acc[e]; be = e; }
        g_top1[n] = be;
        g_val[n]  = best;
        atomicAdd(&g_counts[be], 1);
    }
}

// ---------------- launch 3: fused denom + tile build + scatter --------------
__global__ void k_fuse() {
    const int b = blockIdx.x, tid = threadIdx.x;
    int offs[NE]; int off = 0;
#pragma unroll
    for (int e = 0; e < NE; e++) { offs[e] = off; off += g_counts[e]; }

    const int n = b * 256 + tid;
    const int e = g_top1[n];
    const int pos = atomicAdd(&g_cursor[e], 1);
    g_perm[offs[e] + pos] = n;

    if (b < NE) {
        __shared__ float s[256];
        float p = 0.f;
        for (int i = tid; i < NT; i += 256)
            if (g_top1[i] == b) p += g_val[i];
        s[tid] = p;
        __syncthreads();
        for (int st = 128; st > 0; st >>= 1) {
            if (tid < st) s[tid] += s[tid + st];
            __syncthreads();
        }
        if (tid == 0) g_denom[b] = s[0] + 1e-6f;
    } else if (b == NE && tid == 0) {
        int t = 0;
#pragma unroll
        for (int e2 = 0; e2 < NE; e2++) {
            int c = g_counts[e2];
            for (int r = 0; r < c; r += TMR) {
                g_tile_e[t] = e2; g_tile_start[t] = offs[e2] + r;
                g_tile_rows[t] = (c - r < TMR) ? (c - r) : TMR;
                t++;
            }
        }
        g_ntiles = t;
    }
}

// ---------------- launch 5: convert W2 --------------------------------------
__global__ void k_cvt_w2(const float* __restrict__ W2) {
    __shared__ float t[32][33];
    const int e = blockIdx.z;
    const int c0 = blockIdx.x * 32, r0 = blockIdx.y * 32;
    const int tx = threadIdx.x, ty = threadIdx.y;
    const float* src = W2 + ((size_t)e * FF + r0) * DD + c0;
#pragma unroll
    for (int i = 0; i < 4; i++)
        t[ty + i * 8][tx] = src[(size_t)(ty + i * 8) * DD + tx];
    __syncthreads();
#pragma unroll
    for (int i = 0; i < 4; i++) {
        size_t o = ((size_t)e * DD + c0 + ty + i * 8) * FF + r0 + tx;
        g_w2h[o] = __float2half_rn(t[tx][ty + i * 8]);
    }
}

// ---------------- launches 4 & 6: persistent mma.sync GEMM ------------------
// CTA: 512 threads (16 warps), CTA tile 256x128, warp grid 4(M)x4(N),
// warp tile 64x32. K-chunk 64, 4-stage cp.async pipeline (3-chunk lookahead
// = 192 K-elems). 1 MMA per k-step (A fp16 x W fp16, f32 accum).
#define ROWB 144                   // 64 fp16 = 128 B + 16 pad (conflict-free)
#define A_BYTES 36864              // 256 * 144
#define B_BYTES 18432              // 128 * 144
#define STG_BYTES (A_BYTES + B_BYTES)  // 55296
#define NSTG 4
#define DSMEM (NSTG * STG_BYTES)   // 221184
#define NPERS 148

template <int G>
__global__ __launch_bounds__(512, 1) void k_mma(const float* __restrict__ bias,
                                                float* __restrict__ outp) {
    constexpr int KTOT = (G == 1) ? DD : FF;
    constexpr int NTOT = (G == 1) ? FF : DD;
    constexpr int NKC  = KTOT / 64;
    constexpr int NNY  = NTOT / 128;

    const __half* A  = (G == 1) ? g_xh : g_Hh;
    const __half* Bh = (G == 1) ? g_w1h : g_w2h;

    extern __shared__ char smem[];
    __shared__ int   sPerm[TMR];
    __shared__ float sBias[128];
    const uint32_t dbase = smem_u32(smem);

    const int tid = threadIdx.x;
    const int wid = tid >> 5, lane = tid & 31;
    const int wm = wid & 3, wn = wid >> 2;   // warp tile: rows wm*64, cols wn*32
    // A: 2048 slots (256 rows x 8 segs of 16B), 4 per thread (rows +64 apart)
    const int arow0 = tid >> 3, lsegA = tid & 7;
    // B: 1024 slots (128 rows x 8 segs), 2 per thread
    const int brow0 = tid >> 3;              // 0..63
    const uint32_t aLane = (uint32_t)(wm * 64 + (lane & 15)) * ROWB + ((lane & 16) ? 16 : 0);
    const uint32_t bLane = (uint32_t)(wn * 32 + (lane & 7) + ((lane & 16) ? 8 : 0)) * ROWB
                         + ((lane & 8) ? 16 : 0);
    const int rquad = lane >> 2, cpair = (lane & 3) * 2;

    const int nwork = g_ntiles * NNY;
    for (int w = blockIdx.x; w < nwork; w += NPERS) {
        const int tile = w / NNY, ny = w % NNY;
        const int e     = g_tile_e[tile];
        const int start = g_tile_start[tile];
        const int rows  = g_tile_rows[tile];
        const int n0    = ny * 128;

        __syncthreads();
        if (tid < TMR)
            sPerm[tid] = g_perm[start + (tid < rows ? tid : rows - 1)];
        if (tid < 128)
            sBias[tid] = bias[(size_t)e * NTOT + n0 + tid];
        __syncthreads();

        const __half *pA[4], *pB[2];
        uint32_t lsoA[4], lsoB[2];
#pragma unroll
        for (int i = 0; i < 4; i++) {
            int r = arow0 + 64 * i;
            lsoA[i] = (uint32_t)r * ROWB + lsegA * 16;
            pA[i] = A + (size_t)sPerm[r] * KTOT + lsegA * 8;
        }
#pragma unroll
        for (int i = 0; i < 2; i++) {
            int r = brow0 + 64 * i;
            lsoB[i] = (uint32_t)r * ROWB + lsegA * 16;
            pB[i] = Bh + ((size_t)e * NTOT + n0 + r) * KTOT + lsegA * 8;
        }

        auto load_stage = [&](int c, int s) {
            const int k0 = c * 64;
            const uint32_t d = dbase + s * STG_BYTES;
#pragma unroll
            for (int i = 0; i < 4; i++) cpa16(d + lsoA[i], pA[i] + k0);
#pragma unroll
            for (int i = 0; i < 2; i++) cpa16(d + A_BYTES + lsoB[i], pB[i] + k0);
        };

        float acc[4][4][4];
#pragma unroll
        for (int mi = 0; mi < 4; mi++)
#pragma unroll
            for (int ni = 0; ni < 4; ni++)
#pragma unroll
                for (int q = 0; q < 4; q++) acc[mi][ni][q] = 0.f;

        auto compute = [&](int s) {
            const uint32_t b0 = dbase + s * STG_BYTES;
#pragma unroll
            for (int kh = 0; kh < 4; kh++) {   // 4 k-steps of 16 per 64-chunk
                const uint32_t khb = kh * 32;
                uint32_t ah[4][4], bh[2][4];
#pragma unroll
                for (int mi = 0; mi < 4; mi++)
                    ldmx4(ah[mi], b0 + aLane + mi * (16 * ROWB) + khb);
#pragma unroll
                for (int p = 0; p < 2; p++)
                    ldmx4(bh[p], b0 + A_BYTES + bLane + p * (16 * ROWB) + khb);
#pragma unroll
                for (int mi = 0; mi < 4; mi++)
#pragma unroll
                    for (int ni = 0; ni < 4; ni++)
                        mma_f16(acc[mi][ni], ah[mi], &bh[ni >> 1][(ni & 1) * 2]);
            }
        };

        // prologue: fill NSTG-1 = 3 stages
#pragma unroll
        for (int s = 0; s < NSTG - 1; s++) {
            if (s < NKC) load_stage(s, s);
            CPA_COMMIT();
        }
        for (int c = 0; c < NKC; c++) {
            CPA_WAIT(NSTG - 2);
            __syncthreads();
            if (c + NSTG - 1 < NKC) load_stage(c + NSTG - 1, (c + NSTG - 1) % NSTG);
            CPA_COMMIT();
            compute(c % NSTG);
        }

        // ---- epilogue ----
#pragma unroll
        for (int mi = 0; mi < 4; mi++) {
#pragma unroll
            for (int half = 0; half < 2; half++) {
                const int r = wm * 64 + mi * 16 + rquad + half * 8;
                if (r < rows) {
                    const int token = sPerm[r];
                    if (G == 1) {
#pragma unroll
                        for (int ni = 0; ni < 4; ni++) {
                            const int col = wn * 32 + ni * 8 + cpair;
                            float v0 = fmaxf(acc[mi][ni][half * 2 + 0] + sBias[col], 0.f);
                            float v1 = fmaxf(acc[mi][ni][half * 2 + 1] + sBias[col + 1], 0.f);
                            union { __half h[2]; uint32_t u; } H;
                            H.h[0] = __float2half_rn(v0);
                            H.h[1] = __float2half_rn(v1);
                            *(uint32_t*)(g_Hh + (size_t)token * FF + n0 + col) = H.u;
                        }
                    } else {
                        const float sc = g_val[token] / g_denom[e] * 16384.0f;
#pragma unroll
                        for (int ni = 0; ni < 4; ni++) {
                            const int col = wn * 32 + ni * 8 + cpair;
                            float2 v;
                            v.x = sc * (acc[mi][ni][half * 2 + 0] + sBias[col]);
                            v.y = sc * (acc[mi][ni][half * 2 + 1] + sBias[col + 1]);
                            *(float2*)(outp + (size_t)token * DD + n0 + col) = v;
                        }
                    }
                }
            }
        }
    }
}

// ---------------------------------------------------------------------------
extern "C" void kernel_launch(void* const* d_in, const int* in_sizes, int n_in,
                              void* d_out, int out_size) {
    const float* x  = (const float*)d_in[0];
    const float* Wg = (const float*)d_in[1];
    const float* W1 = (const float*)d_in[2];
    const float* b1 = (const float*)d_in[3];
    const float* W2 = (const float*)d_in[4];
    const float* b2 = (const float*)d_in[5];
    float* out = (float*)d_out;

    static bool configured = false;
    if (!configured) {
        cudaFuncSetAttribute(k_mma<1>, cudaFuncAttributeMaxDynamicSharedMemorySize, DSMEM);
        cudaFuncSetAttribute(k_mma<2>, cudaFuncAttributeMaxDynamicSharedMemorySize, DSMEM);
        configured = true;
    }

    k_cvt_a<<<12288, 256>>>(x, W1);                             // 1
    k_router<<<NT / 8, 256>>>(x, Wg);                           // 2
    k_fuse<<<64, 256>>>();                                      // 3
    k_mma<1><<<NPERS, 512, DSMEM>>>(b1, nullptr);               // 4  <- ncu capture
    k_cvt_w2<<<dim3(DD / 32, FF / 32, NE), dim3(32, 8)>>>(W2);  // 5
    k_mma<2><<<NPERS, 512, DSMEM>>>(b2, out);                   // 6
}